// round 3
// baseline (speedup 1.0000x reference)
#include <cuda_runtime.h>

#define NB 4
#define NC 512
#define CKQ 256
#define NW 64
#define NH 64
#define NN 4096   // H*W

// ---------------- scratch (device globals; no allocation allowed) -----------
__device__ float g_xbar[NB][NC][NW];      // mean over h of x
__device__ float g_x2d [NB][NC][NW];      // interpolated PE-injected row
__device__ float g_krow[NB][CKQ][NW];     // Wk @ x2d + bk
__device__ float g_vbar[NB][NC][NW];      // Wv @ xbar + bv
__device__ float g_M   [NB][NC][NW];      // Wq^T @ krow
__device__ float g_dw  [NB][NW];          // bq . krow
__device__ float g_At  [NB][NW][NN];      // softmax attn, w-major
__device__ float g_part[4][NB][NC][NW];   // split-K partials (deterministic)

// ---------------- K1: xbar[b][c][w] = mean_h x ------------------------------
__global__ void k_xbar(const float* __restrict__ x) {
  int c = blockIdx.x, b = blockIdx.y;
  int tid = threadIdx.x;
  int w = tid & 63, hq = tid >> 6;                 // 256 threads
  const float* xp = x + ((size_t)(b * NC + c)) * NH * NW;
  float s = 0.f;
  #pragma unroll 4
  for (int h = hq; h < NH; h += 4) s += xp[h * NW + w];
  __shared__ float sm[4][64];
  sm[hq][w] = s;
  __syncthreads();
  if (hq == 0)
    g_xbar[b][c][w] = (sm[0][w] + sm[1][w] + sm[2][w] + sm[3][w]) * (1.0f / NH);
}

// ---------------- K2: x1d + PE, interpolate back to W -----------------------
__global__ void k_x2d(const int* __restrict__ pos, const float* __restrict__ pe) {
  int b = blockIdx.x;
  int c = threadIdx.x;                             // 512 threads
  __shared__ int pidx[16];
  if (c < 16) pidx[c] = pos[b * NN + 4 * c] >> 3;  // pos[b][0][4*wp] // 8
  __syncthreads();
  float x1[16];
  #pragma unroll
  for (int wp = 0; wp < 16; wp++) {
    const float* xb = &g_xbar[b][c][4 * wp];
    x1[wp] = 0.25f * (xb[0] + xb[1] + xb[2] + xb[3]) + pe[pidx[wp] * NC + c];
  }
  #pragma unroll
  for (int w = 0; w < NW; w++) {
    float src = (w * 15.0f) / 63.0f;               // same fp32 ops as reference
    int   i0  = (int)floorf(src);
    int   i1  = min(i0 + 1, 15);
    float t   = src - (float)i0;
    g_x2d[b][c][w] = x1[i0] * (1.0f - t) + x1[i1] * t;
  }
}

// ---------------- generic small GEMM: part[ks][b][r][w] = sum_k Aeff(k,r)*X[b][k][w]
// TRANS=false: Aeff(k,r) = A[r*lda + k]   (weight @ activation)
// TRANS=true : Aeff(k,r) = A[k*lda + r]   (weight^T @ activation)
template <bool TRANS>
__global__ void k_gemm_part(const float* __restrict__ A, int lda,
                            const float* __restrict__ X,
                            float* __restrict__ part, int O, int Ktot) {
  int b = blockIdx.y, ks = blockIdx.z;
  int r0 = blockIdx.x * 64;
  int klen = Ktot >> 2;
  int c0base = ks * klen;
  __shared__ float As[16][68];
  __shared__ float Xs[16][68];
  int tid = threadIdx.x, ty = tid >> 4, tx = tid & 15;
  float acc[4][4] = {};
  const float* Xb = X + (size_t)b * Ktot * NW;
  for (int c0 = c0base; c0 < c0base + klen; c0 += 16) {
    if (TRANS) {
      int kk = tid >> 4, r4 = (tid & 15) * 4;
      *(float4*)&As[kk][r4] = *(const float4*)(A + (size_t)(c0 + kk) * lda + r0 + r4);
    } else {
      int rr = tid >> 2, k4 = (tid & 3) * 4;
      float4 v = *(const float4*)(A + (size_t)(r0 + rr) * lda + c0 + k4);
      As[k4 + 0][rr] = v.x; As[k4 + 1][rr] = v.y;
      As[k4 + 2][rr] = v.z; As[k4 + 3][rr] = v.w;
    }
    {
      int kk = tid >> 4, w4 = (tid & 15) * 4;
      *(float4*)&Xs[kk][w4] = *(const float4*)(Xb + (c0 + kk) * NW + w4);
    }
    __syncthreads();
    #pragma unroll
    for (int kk = 0; kk < 16; kk++) {
      float av[4], bv[4];
      *(float4*)av = *(float4*)&As[kk][ty * 4];
      *(float4*)bv = *(float4*)&Xs[kk][tx * 4];
      #pragma unroll
      for (int i = 0; i < 4; i++)
        #pragma unroll
        for (int j = 0; j < 4; j++)
          acc[i][j] = fmaf(av[i], bv[j], acc[i][j]);
    }
    __syncthreads();
  }
  float* pp = part + (((size_t)ks * NB + b) * O + r0) * NW;
  #pragma unroll
  for (int i = 0; i < 4; i++)
    *(float4*)&pp[(ty * 4 + i) * NW + tx * 4] = *(float4*)acc[i];
}

// ---------------- reduce 4 split-K partials + bias --------------------------
__global__ void k_reduce(const float* __restrict__ part, float* __restrict__ dst,
                         const float* __restrict__ bias, int O) {
  int idx = blockIdx.x * 256 + threadIdx.x;
  int total = NB * O * NW;
  if (idx >= total) return;
  int r = (idx >> 6) % O;
  float s = bias ? bias[r] : 0.0f;
  #pragma unroll
  for (int ks = 0; ks < 4; ks++) s += part[(size_t)ks * total + idx];
  dst[idx] = s;
}

// ---------------- dw[b][w] = bq . krow[b][:,w] -------------------------------
__global__ void k_dw(const float* __restrict__ bq) {
  int b = blockIdx.x, w = threadIdx.x;
  float s = 0.f;
  for (int o = 0; o < CKQ; o++) s += bq[o] * g_krow[b][o][w];
  g_dw[b][w] = s;
}

// ---------------- K4a: E = x^T M + dw, softmax over w, write A^T ------------
__global__ void k_attn(const float* __restrict__ x) {
  int b = blockIdx.y;
  int n0 = blockIdx.x * 64;
  __shared__ float As[16][68];
  __shared__ float Bs[16][68];
  __shared__ float Es[64][68];
  int tid = threadIdx.x, ty = tid >> 4, tx = tid & 15;
  float acc[4][4] = {};
  const float* xb = x + (size_t)b * NC * NN + n0;
  for (int c0 = 0; c0 < NC; c0 += 16) {
    int kk = tid >> 4, q4 = (tid & 15) * 4;
    *(float4*)&As[kk][q4] = *(const float4*)(xb + (size_t)(c0 + kk) * NN + q4);
    *(float4*)&Bs[kk][q4] = *(const float4*)(&g_M[b][c0 + kk][q4]);
    __syncthreads();
    #pragma unroll
    for (int kk2 = 0; kk2 < 16; kk2++) {
      float av[4], bv[4];
      *(float4*)av = *(float4*)&As[kk2][ty * 4];
      *(float4*)bv = *(float4*)&Bs[kk2][tx * 4];
      #pragma unroll
      for (int i = 0; i < 4; i++)
        #pragma unroll
        for (int j = 0; j < 4; j++)
          acc[i][j] = fmaf(av[i], bv[j], acc[i][j]);
    }
    __syncthreads();
  }
  #pragma unroll
  for (int i = 0; i < 4; i++)
    #pragma unroll
    for (int j = 0; j < 4; j++)
      Es[ty * 4 + i][tx * 4 + j] = acc[i][j] + g_dw[b][tx * 4 + j];
  __syncthreads();

  // softmax over w per row n: 4 threads per row
  int row = tid >> 2, q = tid & 3;
  float mx = -1e30f;
  for (int w = q; w < NW; w += 4) mx = fmaxf(mx, Es[row][w]);
  mx = fmaxf(mx, __shfl_xor_sync(0xffffffffu, mx, 1));
  mx = fmaxf(mx, __shfl_xor_sync(0xffffffffu, mx, 2));
  float s = 0.f;
  for (int w = q; w < NW; w += 4) {
    float e = __expf(Es[row][w] - mx);
    Es[row][w] = e;
    s += e;
  }
  s += __shfl_xor_sync(0xffffffffu, s, 1);
  s += __shfl_xor_sync(0xffffffffu, s, 2);
  float inv = 1.0f / s;
  for (int w = q; w < NW; w += 4) Es[row][w] *= inv;
  __syncthreads();

  // coalesced transposed store: g_At[b][w][n]
  for (int e = tid; e < 64 * 64; e += 256) {
    int w = e >> 6, nn = e & 63;
    g_At[b][w][n0 + nn] = Es[nn][w];
  }
}

// ---------------- K4b: out = gamma * (vbar @ A^T) + x -----------------------
__global__ void k_out(const float* __restrict__ x, const float* __restrict__ gamma,
                      float* __restrict__ out) {
  int b = blockIdx.z, c0 = blockIdx.y * 64, n0 = blockIdx.x * 64;
  __shared__ float Vs[64][68];   // [c][w]
  __shared__ float Aw[64][68];   // [w][n]
  int tid = threadIdx.x, ty = tid >> 4, tx = tid & 15;
  {
    int base = tid >> 4, q4 = (tid & 15) * 4;
    #pragma unroll
    for (int r = 0; r < 4; r++) {
      int rr = base + r * 16;
      *(float4*)&Vs[rr][q4] = *(const float4*)(&g_vbar[b][c0 + rr][q4]);
      *(float4*)&Aw[rr][q4] = *(const float4*)(&g_At[b][rr][n0 + q4]);
    }
  }
  __syncthreads();
  float acc[4][4] = {};
  #pragma unroll 4
  for (int w = 0; w < NW; w++) {
    float av[4], bv[4];
    #pragma unroll
    for (int i = 0; i < 4; i++) av[i] = Vs[ty * 4 + i][w];
    *(float4*)bv = *(float4*)&Aw[w][tx * 4];
    #pragma unroll
    for (int i = 0; i < 4; i++)
      #pragma unroll
      for (int j = 0; j < 4; j++)
        acc[i][j] = fmaf(av[i], bv[j], acc[i][j]);
  }
  float g = gamma[0];
  #pragma unroll
  for (int i = 0; i < 4; i++) {
    int c = c0 + ty * 4 + i;
    size_t off = (size_t)(b * NC + c) * NN + n0 + tx * 4;
    float4 xv = *(const float4*)(x + off);
    float4 o;
    o.x = fmaf(g, acc[i][0], xv.x);
    o.y = fmaf(g, acc[i][1], xv.y);
    o.z = fmaf(g, acc[i][2], xv.z);
    o.w = fmaf(g, acc[i][3], xv.w);
    *(float4*)(out + off) = o;
  }
}

// ---------------- launch ----------------------------------------------------
extern "C" void kernel_launch(void* const* d_in, const int* in_sizes, int n_in,
                              void* d_out, int out_size) {
  const float* x     = (const float*)d_in[0];
  const float* Wq    = (const float*)d_in[1];
  const float* bq    = (const float*)d_in[2];
  const float* Wk    = (const float*)d_in[3];
  const float* bk    = (const float*)d_in[4];
  const float* Wv    = (const float*)d_in[5];
  const float* bv    = (const float*)d_in[6];
  const float* gamma = (const float*)d_in[7];
  const float* pe    = (const float*)d_in[8];
  const int*   pos   = (const int*)  d_in[9];
  float* out = (float*)d_out;

  void *p_x2d, *p_xbar, *p_krow, *p_vbar, *p_M, *p_part;
  cudaGetSymbolAddress(&p_x2d,  g_x2d);
  cudaGetSymbolAddress(&p_xbar, g_xbar);
  cudaGetSymbolAddress(&p_krow, g_krow);
  cudaGetSymbolAddress(&p_vbar, g_vbar);
  cudaGetSymbolAddress(&p_M,    g_M);
  cudaGetSymbolAddress(&p_part, g_part);

  k_xbar<<<dim3(NC, NB), 256>>>(x);
  k_x2d<<<NB, NC>>>(pos, pe);

  // krow = Wk @ x2d + bk   (O=256, K=512)
  k_gemm_part<false><<<dim3(CKQ / 64, NB, 4), 256>>>(Wk, NC, (const float*)p_x2d,
                                                     (float*)p_part, CKQ, NC);
  k_reduce<<<(NB * CKQ * NW + 255) / 256, 256>>>((const float*)p_part,
                                                 (float*)p_krow, bk, CKQ);
  // vbar = Wv @ xbar + bv  (O=512, K=512)
  k_gemm_part<false><<<dim3(NC / 64, NB, 4), 256>>>(Wv, NC, (const float*)p_xbar,
                                                    (float*)p_part, NC, NC);
  k_reduce<<<(NB * NC * NW + 255) / 256, 256>>>((const float*)p_part,
                                                (float*)p_vbar, bv, NC);
  // M = Wq^T @ krow        (O=512 rows=c, K=256)
  k_gemm_part<true><<<dim3(NC / 64, NB, 4), 256>>>(Wq, NC, (const float*)p_krow,
                                                   (float*)p_part, NC, CKQ);
  k_reduce<<<(NB * NC * NW + 255) / 256, 256>>>((const float*)p_part,
                                                (float*)p_M, nullptr, NC);
  k_dw<<<NB, NW>>>(bq);

  k_attn<<<dim3(NN / 64, NB), 256>>>(x);
  k_out<<<dim3(NN / 64, NC / 64, NB), 256>>>(x, gamma, out);
}

// round 5
// speedup vs baseline: 1.1142x; 1.1142x over previous
#include <cuda_runtime.h>

#define NB 4
#define NC 512
#define CKQ 256
#define NW 64
#define NH 64
#define NN 4096   // H*W

typedef unsigned long long ull;

// ---------------- scratch (device globals) ----------------------------------
__device__ float g_xbar[NB][NC][NW];
__device__ float g_x2d [NB][NC][NW];
__device__ float g_krow[NB][CKQ][NW];
__device__ float g_vbar[NB][NC][NW];
__device__ float g_vbarT[NB][NW][NC];
__device__ float g_M   [NB][NC][NW];
__device__ float g_dw  [NB][NW];
__device__ float g_At  [NB][NW][NN];
__device__ float g_part[4][NB][CKQ + NC][NW];   // split-K partials

// ---------------- f32x2 helpers (Blackwell FFMA2) ---------------------------
__device__ __forceinline__ ull pack2(float v) {
  ull r; asm("mov.b64 %0, {%1, %1};" : "=l"(r) : "f"(v)); return r;
}
__device__ __forceinline__ ull packab(float a, float b) {
  ull r; asm("mov.b64 %0, {%1, %2};" : "=l"(r) : "f"(a), "f"(b)); return r;
}
__device__ __forceinline__ void fma2(ull& d, ull a, ull b) {
  asm("fma.rn.f32x2 %0, %1, %2, %0;" : "+l"(d) : "l"(a), "l"(b));
}
__device__ __forceinline__ void unpack2(ull v, float& lo, float& hi) {
  asm("mov.b64 {%0, %1}, %2;" : "=f"(lo), "=f"(hi) : "l"(v));
}

// ---------------- K1: xbar = mean_h x (float4) ------------------------------
__global__ void k_xbar(const float* __restrict__ x) {
  int c = blockIdx.x, b = blockIdx.y;
  int t = threadIdx.x;
  int hq = t >> 4, tw = t & 15;
  const float* xp = x + ((size_t)(b * NC + c)) * NH * NW;
  float4 s = {0.f, 0.f, 0.f, 0.f};
  #pragma unroll
  for (int h = hq; h < NH; h += 16) {
    float4 v = *(const float4*)&xp[h * NW + tw * 4];
    s.x += v.x; s.y += v.y; s.z += v.z; s.w += v.w;
  }
  __shared__ float4 sm4[16][16];
  sm4[hq][tw] = s;
  __syncthreads();
  if (hq == 0) {
    float4 a = {0.f, 0.f, 0.f, 0.f};
    #pragma unroll
    for (int q = 0; q < 16; q++) {
      float4 v = sm4[q][tw];
      a.x += v.x; a.y += v.y; a.z += v.z; a.w += v.w;
    }
    const float inv = 1.0f / NH;
    a.x *= inv; a.y *= inv; a.z *= inv; a.w *= inv;
    *(float4*)&g_xbar[b][c][tw * 4] = a;
  }
}

// ---------------- K2: x1d + PE, interpolate to W ----------------------------
__global__ void k_x2d(const int* __restrict__ pos, const float* __restrict__ pe) {
  int b = blockIdx.x;
  int c = threadIdx.x;
  __shared__ int pidx[16];
  if (c < 16) pidx[c] = pos[b * NN + 4 * c] >> 3;
  __syncthreads();
  float x1[16];
  #pragma unroll
  for (int wp = 0; wp < 16; wp++) {
    const float* xb = &g_xbar[b][c][4 * wp];
    x1[wp] = 0.25f * (xb[0] + xb[1] + xb[2] + xb[3]) + pe[pidx[wp] * NC + c];
  }
  #pragma unroll
  for (int w = 0; w < NW; w++) {
    float src = (w * 15.0f) / 63.0f;
    int   i0  = (int)floorf(src);
    int   i1  = min(i0 + 1, 15);
    float t   = src - (float)i0;
    g_x2d[b][c][w] = x1[i0] * (1.0f - t) + x1[i1] * t;
  }
}

// ---------------- combined krow/vbar split-K GEMM ---------------------------
// blockIdx.x < 4  : krow part rows r0=x*64       (A=Wk, X=x2d)
// blockIdx.x >= 4 : vbar part rows r0=(x-4)*64   (A=Wv, X=xbar), out offset 256
__global__ void k_gemmKV(const float* __restrict__ Wk, const float* __restrict__ Wv) {
  bool vb = (blockIdx.x >= 4);
  const float* A = vb ? Wv : Wk;
  const float* X = vb ? &g_xbar[0][0][0] : &g_x2d[0][0][0];
  int r0   = (vb ? (int)blockIdx.x - 4 : (int)blockIdx.x) * 64;
  int rout = vb ? CKQ + r0 : r0;
  int b = blockIdx.y, ks = blockIdx.z;
  int c0base = ks * 128;
  __shared__ float As[16][68];
  __shared__ float Xs[16][68];
  int tid = threadIdx.x, ty = tid >> 4, tx = tid & 15;
  float acc[4][4] = {};
  const float* Xb = X + (size_t)b * NC * NW;
  for (int c0 = c0base; c0 < c0base + 128; c0 += 16) {
    {
      int rr = tid >> 2, k4 = (tid & 3) * 4;
      float4 v = *(const float4*)(A + (size_t)(r0 + rr) * NC + c0 + k4);
      As[k4 + 0][rr] = v.x; As[k4 + 1][rr] = v.y;
      As[k4 + 2][rr] = v.z; As[k4 + 3][rr] = v.w;
    }
    {
      int kk = tid >> 4, w4 = (tid & 15) * 4;
      *(float4*)&Xs[kk][w4] = *(const float4*)(Xb + (c0 + kk) * NW + w4);
    }
    __syncthreads();
    #pragma unroll
    for (int kk = 0; kk < 16; kk++) {
      float av[4], bv[4];
      *(float4*)av = *(float4*)&As[kk][ty * 4];
      *(float4*)bv = *(float4*)&Xs[kk][tx * 4];
      #pragma unroll
      for (int i = 0; i < 4; i++)
        #pragma unroll
        for (int j = 0; j < 4; j++)
          acc[i][j] = fmaf(av[i], bv[j], acc[i][j]);
    }
    __syncthreads();
  }
  float* pp = &g_part[ks][b][rout][0];
  #pragma unroll
  for (int i = 0; i < 4; i++)
    *(float4*)&pp[(ty * 4 + i) * NW + tx * 4] = *(float4*)acc[i];
}

// ---------------- reduce krow/vbar parts + biases; also emit vbar^T ---------
__global__ void k_reduceKV(const float* __restrict__ bk, const float* __restrict__ bv) {
  int idx = blockIdx.x * 256 + threadIdx.x;
  const int total = NB * (CKQ + NC) * NW;
  if (idx >= total) return;
  int b = idx / ((CKQ + NC) * NW);
  int r = (idx >> 6) % (CKQ + NC);
  int w = idx & 63;
  float s = 0.f;
  #pragma unroll
  for (int ks = 0; ks < 4; ks++) s += (&g_part[ks][0][0][0])[(size_t)b * (CKQ + NC) * NW + (idx - (size_t)b * (CKQ + NC) * NW)];
  if (r < CKQ) {
    g_krow[b][r][w] = s + bk[r];
  } else {
    int c = r - CKQ;
    float v = s + bv[c];
    g_vbar[b][c][w] = v;
    g_vbarT[b][w][c] = v;
  }
}

// ---------------- M = Wq^T @ krow (split-K parts) ---------------------------
__global__ void k_gemmM(const float* __restrict__ Wq) {
  int b = blockIdx.y, ks = blockIdx.z;
  int r0 = blockIdx.x * 64;
  int c0base = ks * 64;                 // Ktot=256, klen=64
  __shared__ float As[16][68];
  __shared__ float Xs[16][68];
  int tid = threadIdx.x, ty = tid >> 4, tx = tid & 15;
  float acc[4][4] = {};
  for (int c0 = c0base; c0 < c0base + 64; c0 += 16) {
    {
      int kk = tid >> 4, r4 = (tid & 15) * 4;
      *(float4*)&As[kk][r4] = *(const float4*)(Wq + (size_t)(c0 + kk) * NC + r0 + r4);
    }
    {
      int kk = tid >> 4, w4 = (tid & 15) * 4;
      *(float4*)&Xs[kk][w4] = *(const float4*)(&g_krow[b][c0 + kk][w4]);
    }
    __syncthreads();
    #pragma unroll
    for (int kk = 0; kk < 16; kk++) {
      float av[4], bv[4];
      *(float4*)av = *(float4*)&As[kk][ty * 4];
      *(float4*)bv = *(float4*)&Xs[kk][tx * 4];
      #pragma unroll
      for (int i = 0; i < 4; i++)
        #pragma unroll
        for (int j = 0; j < 4; j++)
          acc[i][j] = fmaf(av[i], bv[j], acc[i][j]);
    }
    __syncthreads();
  }
  float* pp = &g_part[ks][b][r0][0];    // stride uses (CKQ+NC) rows; rows 0..511 used
  #pragma unroll
  for (int i = 0; i < 4; i++)
    *(float4*)&pp[(ty * 4 + i) * NW + tx * 4] = *(float4*)acc[i];
}

// ---------------- reduce M parts; extra block computes dw -------------------
__global__ void k_reduceM(const float* __restrict__ bq) {
  if (blockIdx.x == 512) {              // dw block
    int t = threadIdx.x;
    int b = t >> 6, w = t & 63;
    float s = 0.f;
    #pragma unroll 4
    for (int o = 0; o < CKQ; o++) s += bq[o] * g_krow[b][o][w];
    g_dw[b][w] = s;
    return;
  }
  int idx = blockIdx.x * 256 + threadIdx.x;
  int b = idx / (NC * NW);
  int rw = idx - b * NC * NW;           // r*64+w with r<512
  float s = 0.f;
  #pragma unroll
  for (int ks = 0; ks < 4; ks++)
    s += (&g_part[ks][b][0][0])[rw];
  (&g_M[b][0][0])[rw] = s;
}

// ---------------- K4a: E = x^T M + dw, softmax, write A^T (FFMA2) -----------
// block: 256 thr, tile 128n x 64w; per-thread 8n x 4w, pairs packed along n.
__global__ void k_attn(const float* __restrict__ x) {
  int b = blockIdx.y;
  int n0 = blockIdx.x * 128;
  __shared__ float sm[128 * 66];        // Es region; aliases xs, Ms
  float* xs = sm;                       // [16][132]
  float* Ms = sm + 16 * 132;            // [16][68]
  int tid = threadIdx.x;
  int ty = tid >> 4, tx = tid & 15;

  ull acc[4][4];
  #pragma unroll
  for (int i = 0; i < 4; i++)
    #pragma unroll
    for (int j = 0; j < 4; j++) acc[i][j] = 0ull;

  const float* xb = x + (size_t)b * NC * NN + n0;
  int lk = tid >> 4, lc = (tid & 15) * 8;     // x-tile loader coords
  int mw = (tid & 15) * 4;                    // M-tile loader coords

  for (int c0 = 0; c0 < NC; c0 += 16) {
    *(float4*)&xs[lk * 132 + lc]     = *(const float4*)(xb + (size_t)(c0 + lk) * NN + lc);
    *(float4*)&xs[lk * 132 + lc + 4] = *(const float4*)(xb + (size_t)(c0 + lk) * NN + lc + 4);
    *(float4*)&Ms[lk * 68 + mw]      = *(const float4*)(&g_M[b][c0 + lk][mw]);
    __syncthreads();
    #pragma unroll 4
    for (int k = 0; k < 16; k++) {
      float4 a0 = *(const float4*)&xs[k * 132 + ty * 8];
      float4 a1 = *(const float4*)&xs[k * 132 + ty * 8 + 4];
      float4 bv = *(const float4*)&Ms[k * 68 + tx * 4];
      ull ap[4] = {packab(a0.x, a0.y), packab(a0.z, a0.w),
                   packab(a1.x, a1.y), packab(a1.z, a1.w)};
      ull bd[4] = {pack2(bv.x), pack2(bv.y), pack2(bv.z), pack2(bv.w)};
      #pragma unroll
      for (int i = 0; i < 4; i++)
        #pragma unroll
        for (int j = 0; j < 4; j++)
          fma2(acc[i][j], ap[i], bd[j]);
    }
    __syncthreads();
  }

  // epilogue: Es[n][w] = acc + dw[w]
  float dwv[4];
  #pragma unroll
  for (int j = 0; j < 4; j++) dwv[j] = g_dw[b][tx * 4 + j];
  float* Es = sm;                       // [128][66]
  #pragma unroll
  for (int i = 0; i < 4; i++) {
    int nl = ty * 8 + 2 * i;
    #pragma unroll
    for (int j = 0; j < 4; j++) {
      float lo, hi;
      unpack2(acc[i][j], lo, hi);
      Es[nl * 66 + tx * 4 + j]       = lo + dwv[j];
      Es[(nl + 1) * 66 + tx * 4 + j] = hi + dwv[j];
    }
  }
  __syncthreads();

  // softmax over w (2 threads per row)
  int row = tid >> 1, q = tid & 1;
  float mx = -1e30f;
  for (int w = q; w < NW; w += 2) mx = fmaxf(mx, Es[row * 66 + w]);
  mx = fmaxf(mx, __shfl_xor_sync(0xffffffffu, mx, 1));
  float s = 0.f;
  for (int w = q; w < NW; w += 2) {
    float e = __expf(Es[row * 66 + w] - mx);
    Es[row * 66 + w] = e;
    s += e;
  }
  s += __shfl_xor_sync(0xffffffffu, s, 1);
  float inv = 1.0f / s;
  for (int w = q; w < NW; w += 2) Es[row * 66 + w] *= inv;
  __syncthreads();

  // transposed store, coalesced along n
  for (int e = tid; e < 128 * 64; e += 256) {
    int w = e >> 7, nn = e & 127;
    g_At[b][w][n0 + nn] = Es[nn * 66 + w];
  }
}

// ---------------- K4b: out = gamma*(vbar @ A^T) + x (FFMA2) -----------------
// block: 256 thr, tile 128c x 64n; per-thread 8c x 4n, pairs packed along c.
__global__ void k_out(const float* __restrict__ x, const float* __restrict__ gamma,
                      float* __restrict__ out) {
  int b = blockIdx.z, c0 = blockIdx.y * 128, n0 = blockIdx.x * 64;
  __shared__ float Vt[64 * 128];        // [w][c]
  __shared__ float Aw[64 * 64];         // [w][n]
  int tid = threadIdx.x;
  int ty = tid >> 4, tx = tid & 15;

  // load Vt tile (64w x 128c) and At tile (64w x 64n)
  #pragma unroll
  for (int t = 0; t < 8; t++) {
    int e = tid + t * 256;              // over 2048 float4
    int w = e >> 5, c4 = (e & 31) * 4;
    *(float4*)&Vt[w * 128 + c4] = *(const float4*)(&g_vbarT[b][w][c0 + c4]);
  }
  #pragma unroll
  for (int t = 0; t < 4; t++) {
    int e = tid + t * 256;              // over 1024 float4
    int w = e >> 4, n4 = (e & 15) * 4;
    *(float4*)&Aw[w * 64 + n4] = *(const float4*)(&g_At[b][w][n0 + n4]);
  }
  __syncthreads();

  ull acc[4][4];
  #pragma unroll
  for (int i = 0; i < 4; i++)
    #pragma unroll
    for (int j = 0; j < 4; j++) acc[i][j] = 0ull;

  #pragma unroll 4
  for (int k = 0; k < NW; k++) {
    float4 a0 = *(const float4*)&Vt[k * 128 + ty * 8];
    float4 a1 = *(const float4*)&Vt[k * 128 + ty * 8 + 4];
    float4 bv = *(const float4*)&Aw[k * 64 + tx * 4];
    ull ap[4] = {packab(a0.x, a0.y), packab(a0.z, a0.w),
                 packab(a1.x, a1.y), packab(a1.z, a1.w)};
    ull bd[4] = {pack2(bv.x), pack2(bv.y), pack2(bv.z), pack2(bv.w)};
    #pragma unroll
    for (int i = 0; i < 4; i++)
      #pragma unroll
      for (int j = 0; j < 4; j++)
        fma2(acc[i][j], ap[i], bd[j]);
  }

  float g = gamma[0];
  #pragma unroll
  for (int i = 0; i < 4; i++) {
    int c = c0 + ty * 8 + 2 * i;
    float r0[4], r1[4];
    #pragma unroll
    for (int j = 0; j < 4; j++) unpack2(acc[i][j], r0[j], r1[j]);
    size_t off0 = (size_t)(b * NC + c) * NN + n0 + tx * 4;
    size_t off1 = off0 + NN;
    float4 xv0 = *(const float4*)(x + off0);
    float4 xv1 = *(const float4*)(x + off1);
    float4 o0, o1;
    o0.x = fmaf(g, r0[0], xv0.x); o0.y = fmaf(g, r0[1], xv0.y);
    o0.z = fmaf(g, r0[2], xv0.z); o0.w = fmaf(g, r0[3], xv0.w);
    o1.x = fmaf(g, r1[0], xv1.x); o1.y = fmaf(g, r1[1], xv1.y);
    o1.z = fmaf(g, r1[2], xv1.z); o1.w = fmaf(g, r1[3], xv1.w);
    *(float4*)(out + off0) = o0;
    *(float4*)(out + off1) = o1;
  }
}

// ---------------- launch ----------------------------------------------------
extern "C" void kernel_launch(void* const* d_in, const int* in_sizes, int n_in,
                              void* d_out, int out_size) {
  const float* x     = (const float*)d_in[0];
  const float* Wq    = (const float*)d_in[1];
  const float* bq    = (const float*)d_in[2];
  const float* Wk    = (const float*)d_in[3];
  const float* bk    = (const float*)d_in[4];
  const float* Wv    = (const float*)d_in[5];
  const float* bv    = (const float*)d_in[6];
  const float* gamma = (const float*)d_in[7];
  const float* pe    = (const float*)d_in[8];
  const int*   pos   = (const int*)  d_in[9];
  float* out = (float*)d_out;

  k_xbar<<<dim3(NC, NB), 256>>>(x);
  k_x2d<<<NB, NC>>>(pos, pe);
  k_gemmKV<<<dim3(12, NB, 4), 256>>>(Wk, Wv);
  k_reduceKV<<<(NB * (CKQ + NC) * NW + 255) / 256, 256>>>(bk, bv);
  k_gemmM<<<dim3(NC / 64, NB, 4), 256>>>(Wq);
  k_reduceM<<<513, 256>>>(bq);
  k_attn<<<dim3(NN / 128, NB), 256>>>(x);
  k_out<<<dim3(NN / 64, NC / 128, NB), 256>>>(x, gamma, out);
}

// round 6
// speedup vs baseline: 1.2340x; 1.1075x over previous
#include <cuda_runtime.h>
#include <cuda_bf16.h>

#define NB 4
#define NC 512
#define CKQ 256
#define NW 64
#define NH 64
#define NN 4096   // H*W

// ---------------- scratch (device globals) ----------------------------------
__device__ float g_xbar[NB][NC][NW];
__device__ float g_x2d [NB][NC][NW];
__device__ float g_krow[NB][CKQ][NW];
__device__ float g_dw  [NB][NW];
__device__ float g_part[4][NB][CKQ + NC][NW];   // split-K partials (KV)
__device__ float g_pM  [4][NB][NW][NC];         // split-K partials (M, transposed)
__device__ __nv_bfloat16 g_MTh[NB][NW][NC];     // M^T hi/lo bf16
__device__ __nv_bfloat16 g_MTl[NB][NW][NC];
__device__ __nv_bfloat16 g_vbh[NB][NC][NW];     // vbar hi/lo bf16
__device__ __nv_bfloat16 g_vbl[NB][NC][NW];

// ---------------- helpers ----------------------------------------------------
__device__ __forceinline__ unsigned pack_bf2(float e, float o) {
  __nv_bfloat162 h;
  h.x = __float2bfloat16(e);   // low half  = even k
  h.y = __float2bfloat16(o);   // high half = odd k
  return *reinterpret_cast<unsigned*>(&h);
}
__device__ __forceinline__ void ldsm4(unsigned& r0, unsigned& r1, unsigned& r2,
                                      unsigned& r3, unsigned addr) {
  asm volatile("ldmatrix.sync.aligned.m8n8.x4.shared.b16 {%0,%1,%2,%3},[%4];"
               : "=r"(r0), "=r"(r1), "=r"(r2), "=r"(r3) : "r"(addr));
}
__device__ __forceinline__ void mma16816(float* d, const unsigned* a,
                                         unsigned b0, unsigned b1) {
  asm volatile(
    "mma.sync.aligned.m16n8k16.row.col.f32.bf16.bf16.f32 "
    "{%0,%1,%2,%3},{%4,%5,%6,%7},{%8,%9},{%0,%1,%2,%3};"
    : "+f"(d[0]), "+f"(d[1]), "+f"(d[2]), "+f"(d[3])
    : "r"(a[0]), "r"(a[1]), "r"(a[2]), "r"(a[3]), "r"(b0), "r"(b1));
}

// ---------------- K1: xbar = mean_h x ----------------------------------------
__global__ void k_xbar(const float* __restrict__ x) {
  int c = blockIdx.x, b = blockIdx.y;
  int t = threadIdx.x;
  int hq = t >> 4, tw = t & 15;
  const float* xp = x + ((size_t)(b * NC + c)) * NH * NW;
  float4 s = {0.f, 0.f, 0.f, 0.f};
  #pragma unroll
  for (int h = hq; h < NH; h += 16) {
    float4 v = *(const float4*)&xp[h * NW + tw * 4];
    s.x += v.x; s.y += v.y; s.z += v.z; s.w += v.w;
  }
  __shared__ float4 sm4[16][16];
  sm4[hq][tw] = s;
  __syncthreads();
  if (hq == 0) {
    float4 a = {0.f, 0.f, 0.f, 0.f};
    #pragma unroll
    for (int q = 0; q < 16; q++) {
      float4 v = sm4[q][tw];
      a.x += v.x; a.y += v.y; a.z += v.z; a.w += v.w;
    }
    const float inv = 1.0f / NH;
    a.x *= inv; a.y *= inv; a.z *= inv; a.w *= inv;
    *(float4*)&g_xbar[b][c][tw * 4] = a;
  }
}

// ---------------- K2: x1d + PE, interpolate to W -----------------------------
__global__ void k_x2d(const int* __restrict__ pos, const float* __restrict__ pe) {
  int b = blockIdx.x;
  int c = threadIdx.x;
  __shared__ int pidx[16];
  if (c < 16) pidx[c] = pos[b * NN + 4 * c] >> 3;
  __syncthreads();
  float x1[16];
  #pragma unroll
  for (int wp = 0; wp < 16; wp++) {
    const float* xb = &g_xbar[b][c][4 * wp];
    x1[wp] = 0.25f * (xb[0] + xb[1] + xb[2] + xb[3]) + pe[pidx[wp] * NC + c];
  }
  #pragma unroll
  for (int w = 0; w < NW; w++) {
    float src = (w * 15.0f) / 63.0f;
    int   i0  = (int)floorf(src);
    int   i1  = min(i0 + 1, 15);
    float t   = src - (float)i0;
    g_x2d[b][c][w] = x1[i0] * (1.0f - t) + x1[i1] * t;
  }
}

// ---------------- combined krow/vbar split-K GEMM ----------------------------
__global__ void k_gemmKV(const float* __restrict__ Wk, const float* __restrict__ Wv) {
  bool vb = (blockIdx.x >= 4);
  const float* A = vb ? Wv : Wk;
  const float* X = vb ? &g_xbar[0][0][0] : &g_x2d[0][0][0];
  int r0   = (vb ? (int)blockIdx.x - 4 : (int)blockIdx.x) * 64;
  int rout = vb ? CKQ + r0 : r0;
  int b = blockIdx.y, ks = blockIdx.z;
  int c0base = ks * 128;
  __shared__ float As[16][68];
  __shared__ float Xs[16][68];
  int tid = threadIdx.x, ty = tid >> 4, tx = tid & 15;
  float acc[4][4] = {};
  const float* Xb = X + (size_t)b * NC * NW;
  for (int c0 = c0base; c0 < c0base + 128; c0 += 16) {
    {
      int rr = tid >> 2, k4 = (tid & 3) * 4;
      float4 v = *(const float4*)(A + (size_t)(r0 + rr) * NC + c0 + k4);
      As[k4 + 0][rr] = v.x; As[k4 + 1][rr] = v.y;
      As[k4 + 2][rr] = v.z; As[k4 + 3][rr] = v.w;
    }
    {
      int kk = tid >> 4, w4 = (tid & 15) * 4;
      *(float4*)&Xs[kk][w4] = *(const float4*)(Xb + (c0 + kk) * NW + w4);
    }
    __syncthreads();
    #pragma unroll
    for (int kk = 0; kk < 16; kk++) {
      float av[4], bv[4];
      *(float4*)av = *(float4*)&As[kk][ty * 4];
      *(float4*)bv = *(float4*)&Xs[kk][tx * 4];
      #pragma unroll
      for (int i = 0; i < 4; i++)
        #pragma unroll
        for (int j = 0; j < 4; j++)
          acc[i][j] = fmaf(av[i], bv[j], acc[i][j]);
    }
    __syncthreads();
  }
  float* pp = &g_part[ks][b][rout][0];
  #pragma unroll
  for (int i = 0; i < 4; i++)
    *(float4*)&pp[(ty * 4 + i) * NW + tx * 4] = *(float4*)acc[i];
}

// ---------------- reduce krow/vbar; emit krow f32, vbar bf16 hi/lo ----------
__global__ void k_reduceKV(const float* __restrict__ bk, const float* __restrict__ bv) {
  int idx = blockIdx.x * 256 + threadIdx.x;
  const int total = NB * (CKQ + NC) * NW;
  if (idx >= total) return;
  int b = idx / ((CKQ + NC) * NW);
  int rw = idx - b * (CKQ + NC) * NW;
  int r = rw >> 6, w = idx & 63;
  float s = 0.f;
  #pragma unroll
  for (int ks = 0; ks < 4; ks++) s += (&g_part[ks][b][0][0])[rw];
  if (r < CKQ) {
    g_krow[b][r][w] = s + bk[r];
  } else {
    int c = r - CKQ;
    float v = s + bv[c];
    __nv_bfloat16 h = __float2bfloat16(v);
    g_vbh[b][c][w] = h;
    g_vbl[b][c][w] = __float2bfloat16(v - __bfloat162float(h));
  }
}

// ---------------- M^T parts = (Wq^T @ krow)^T --------------------------------
__global__ void k_gemmM(const float* __restrict__ Wq) {
  int b = blockIdx.y, ks = blockIdx.z;
  int r0 = blockIdx.x * 64;
  int c0base = ks * 64;                 // Ktot=256
  __shared__ float As[16][68];
  __shared__ float Xs[16][68];
  int tid = threadIdx.x, ty = tid >> 4, tx = tid & 15;
  float acc[4][4] = {};
  for (int c0 = c0base; c0 < c0base + 64; c0 += 16) {
    {
      int kk = tid >> 4, r4 = (tid & 15) * 4;
      *(float4*)&As[kk][r4] = *(const float4*)(Wq + (size_t)(c0 + kk) * NC + r0 + r4);
    }
    {
      int kk = tid >> 4, w4 = (tid & 15) * 4;
      *(float4*)&Xs[kk][w4] = *(const float4*)(&g_krow[b][c0 + kk][w4]);
    }
    __syncthreads();
    #pragma unroll
    for (int kk = 0; kk < 16; kk++) {
      float av[4], bv[4];
      *(float4*)av = *(float4*)&As[kk][ty * 4];
      *(float4*)bv = *(float4*)&Xs[kk][tx * 4];
      #pragma unroll
      for (int i = 0; i < 4; i++)
        #pragma unroll
        for (int j = 0; j < 4; j++)
          acc[i][j] = fmaf(av[i], bv[j], acc[i][j]);
    }
    __syncthreads();
  }
  #pragma unroll
  for (int i = 0; i < 4; i++)
    #pragma unroll
    for (int j = 0; j < 4; j++)
      g_pM[ks][b][tx * 4 + j][r0 + ty * 4 + i] = acc[i][j];
}

// ---------------- reduce M^T parts -> bf16 hi/lo; extra block = dw -----------
__global__ void k_reduceM(const float* __restrict__ bq) {
  if (blockIdx.x == 512) {
    int t = threadIdx.x;
    int b = t >> 6, w = t & 63;
    float s = 0.f;
    #pragma unroll 4
    for (int o = 0; o < CKQ; o++) s += bq[o] * g_krow[b][o][w];
    g_dw[b][w] = s;
    return;
  }
  int idx = blockIdx.x * 256 + threadIdx.x;      // < 131072
  int b = idx >> 15;                             // NW*NC = 32768
  int rem = idx & 32767;
  float s = 0.f;
  #pragma unroll
  for (int ks = 0; ks < 4; ks++) s += (&g_pM[ks][b][0][0])[rem];
  __nv_bfloat16 h = __float2bfloat16(s);
  (&g_MTh[b][0][0])[rem] = h;
  (&g_MTl[b][0][0])[rem] = __float2bfloat16(s - __bfloat162float(h));
}

// ---------------- fused: E = x^T M + dw, softmax, out = g*(vbar@A^T)+x -------
// grid (32, NB), 256 threads. n-tile = 128. Tensor cores (mma m16n8k16 bf16).
#define XA_H 0
#define XA_L 10240
#define MB_H 20480
#define MB_L 25600
#define OFF_E 36864
#define ATT_H 0
#define ATT_L 18432
#define VB_H 36864
#define VB_L 55296
#define SMEM_FUSED 73728

__global__ __launch_bounds__(256)
void k_fused(const float* __restrict__ x, const float* __restrict__ gamma,
             float* __restrict__ out) {
  extern __shared__ char sm[];
  unsigned sb = (unsigned)__cvta_generic_to_shared(sm);
  int tid = threadIdx.x;
  int wid = tid >> 5, lane = tid & 31;
  int b = blockIdx.y;
  int n0 = blockIdx.x * 128;
  int gI = lane >> 2, tq = lane & 3;

  // ---------------- phase 1: E[128n][64w] -----------------------------------
  int ny = (wid >> 1) * 32;        // warp n-offset
  int wy = (wid & 1) * 32;         // warp w-offset
  float acc1[2][4][4] = {};
  const float* xb = x + (size_t)b * NC * NN + n0;

  for (int c0 = 0; c0 < NC; c0 += 32) {
    // load+convert+transpose x tile [32c][128n] -> XA (hi/lo bf16, [n][40k])
    #pragma unroll
    for (int it = tid; it < 512; it += 256) {
      int c2 = it >> 5, n4 = it & 31;
      const float* p0 = xb + (size_t)(c0 + 2 * c2) * NN + n4 * 4;
      float4 f0 = *(const float4*)p0;
      float4 f1 = *(const float4*)(p0 + NN);
      float a0[4] = {f0.x, f0.y, f0.z, f0.w};
      float a1[4] = {f1.x, f1.y, f1.z, f1.w};
      #pragma unroll
      for (int j = 0; j < 4; j++) {
        int n = n4 * 4 + j;
        float h0 = __bfloat162float(__float2bfloat16(a0[j]));
        float h1 = __bfloat162float(__float2bfloat16(a1[j]));
        ((unsigned*)(sm + XA_H))[n * 20 + c2] = pack_bf2(a0[j], a1[j]);
        ((unsigned*)(sm + XA_L))[n * 20 + c2] = pack_bf2(a0[j] - h0, a1[j] - h1);
      }
    }
    // load M^T tile [64w][32c] hi/lo
    {
      int w = tid >> 2, q = tid & 3;
      ((uint4*)(sm + MB_H))[w * 5 + q] = *(const uint4*)&g_MTh[b][w][c0 + q * 8];
      ((uint4*)(sm + MB_L))[w * 5 + q] = *(const uint4*)&g_MTl[b][w][c0 + q * 8];
    }
    __syncthreads();

    #pragma unroll
    for (int ks = 0; ks < 32; ks += 16) {
      unsigned Ah[2][4], Al[2][4];
      #pragma unroll
      for (int mt = 0; mt < 2; mt++) {
        unsigned row = ny + mt * 16 + (lane & 15);
        unsigned coff = ks * 2 + ((lane >> 4) << 4);
        ldsm4(Ah[mt][0], Ah[mt][1], Ah[mt][2], Ah[mt][3], sb + XA_H + row * 80 + coff);
        ldsm4(Al[mt][0], Al[mt][1], Al[mt][2], Al[mt][3], sb + XA_L + row * 80 + coff);
      }
      unsigned Bh[2][4], Bl[2][4];
      #pragma unroll
      for (int bt = 0; bt < 2; bt++) {
        unsigned row = wy + bt * 16 + (lane & 7) + ((lane & 16) >> 1);
        unsigned coff = ks * 2 + ((lane & 8) << 1);
        ldsm4(Bh[bt][0], Bh[bt][1], Bh[bt][2], Bh[bt][3], sb + MB_H + row * 80 + coff);
        ldsm4(Bl[bt][0], Bl[bt][1], Bl[bt][2], Bl[bt][3], sb + MB_L + row * 80 + coff);
      }
      #pragma unroll
      for (int mt = 0; mt < 2; mt++)
        #pragma unroll
        for (int bt = 0; bt < 2; bt++)
          #pragma unroll
          for (int sub = 0; sub < 2; sub++) {
            int wt = bt * 2 + sub;
            mma16816(acc1[mt][wt], Ah[mt], Bh[bt][sub * 2], Bh[bt][sub * 2 + 1]);
            mma16816(acc1[mt][wt], Ah[mt], Bl[bt][sub * 2], Bl[bt][sub * 2 + 1]);
            mma16816(acc1[mt][wt], Al[mt], Bh[bt][sub * 2], Bh[bt][sub * 2 + 1]);
          }
    }
    __syncthreads();
  }

  // epilogue: E += dw, stage to smem
  float* Ef = (float*)(sm + OFF_E);
  #pragma unroll
  for (int wt = 0; wt < 4; wt++) {
    int wc = wy + wt * 8 + 2 * tq;
    float d0 = g_dw[b][wc], d1 = g_dw[b][wc + 1];
    #pragma unroll
    for (int mt = 0; mt < 2; mt++) {
      int r = ny + mt * 16 + gI;
      float2 v0 = {acc1[mt][wt][0] + d0, acc1[mt][wt][1] + d1};
      float2 v1 = {acc1[mt][wt][2] + d0, acc1[mt][wt][3] + d1};
      *(float2*)&Ef[r * 68 + wc] = v0;
      *(float2*)&Ef[(r + 8) * 68 + wc] = v1;
    }
  }
  __syncthreads();

  // softmax over w (2 threads/row)
  {
    int row = tid >> 1, q = tid & 1;
    float mx = -1e30f;
    for (int w = q; w < NW; w += 2) mx = fmaxf(mx, Ef[row * 68 + w]);
    mx = fmaxf(mx, __shfl_xor_sync(0xffffffffu, mx, 1));
    float s = 0.f;
    for (int w = q; w < NW; w += 2) {
      float e = __expf(Ef[row * 68 + w] - mx);
      Ef[row * 68 + w] = e;
      s += e;
    }
    s += __shfl_xor_sync(0xffffffffu, s, 1);
    float inv = 1.0f / s;
    for (int w = q; w < NW; w += 2) Ef[row * 68 + w] *= inv;
  }
  __syncthreads();

  // convert attn to bf16 hi/lo [n][72]
  #pragma unroll
  for (int i = 0; i < 16; i++) {
    int p = tid + i * 256;
    int n = p >> 5, wp = p & 31;
    float e0 = Ef[n * 68 + 2 * wp], e1 = Ef[n * 68 + 2 * wp + 1];
    float h0 = __bfloat162float(__float2bfloat16(e0));
    float h1 = __bfloat162float(__float2bfloat16(e1));
    ((unsigned*)(sm + ATT_H))[n * 36 + wp] = pack_bf2(e0, e1);
    ((unsigned*)(sm + ATT_L))[n * 36 + wp] = pack_bf2(e0 - h0, e1 - h1);
  }

  // ---------------- phase 2: out = gamma*(vbar @ A^T) + x --------------------
  float g = gamma[0];
  int cy = (wid >> 1) * 32;        // warp c-offset within 128-chunk
  int nx = (wid & 1) * 64;         // warp n-offset within 128-tile
  for (int cc = 0; cc < 4; cc++) {
    __syncthreads();               // ATT ready / previous chunk done reading VB
    #pragma unroll
    for (int it = tid; it < 1024; it += 256) {
      int rr = it >> 3, q = it & 7;
      ((uint4*)(sm + VB_H))[rr * 9 + q] = *(const uint4*)&g_vbh[b][cc * 128 + rr][q * 8];
      ((uint4*)(sm + VB_L))[rr * 9 + q] = *(const uint4*)&g_vbl[b][cc * 128 + rr][q * 8];
    }
    __syncthreads();

    float acc2[2][8][4] = {};
    #pragma unroll
    for (int ks = 0; ks < 64; ks += 16) {
      unsigned Ah[2][4], Al[2][4];
      #pragma unroll
      for (int mt = 0; mt < 2; mt++) {
        unsigned row = cy + mt * 16 + (lane & 15);
        unsigned coff = ks * 2 + ((lane >> 4) << 4);
        ldsm4(Ah[mt][0], Ah[mt][1], Ah[mt][2], Ah[mt][3], sb + VB_H + row * 144 + coff);
        ldsm4(Al[mt][0], Al[mt][1], Al[mt][2], Al[mt][3], sb + VB_L + row * 144 + coff);
      }
      unsigned Bh[4][4], Bl[4][4];
      #pragma unroll
      for (int bt = 0; bt < 4; bt++) {
        unsigned row = nx + bt * 16 + (lane & 7) + ((lane & 16) >> 1);
        unsigned coff = ks * 2 + ((lane & 8) << 1);
        ldsm4(Bh[bt][0], Bh[bt][1], Bh[bt][2], Bh[bt][3], sb + ATT_H + row * 144 + coff);
        ldsm4(Bl[bt][0], Bl[bt][1], Bl[bt][2], Bl[bt][3], sb + ATT_L + row * 144 + coff);
      }
      #pragma unroll
      for (int mt = 0; mt < 2; mt++)
        #pragma unroll
        for (int bt = 0; bt < 4; bt++)
          #pragma unroll
          for (int sub = 0; sub < 2; sub++) {
            int nt = bt * 2 + sub;
            mma16816(acc2[mt][nt], Ah[mt], Bh[bt][sub * 2], Bh[bt][sub * 2 + 1]);
            mma16816(acc2[mt][nt], Ah[mt], Bl[bt][sub * 2], Bl[bt][sub * 2 + 1]);
            mma16816(acc2[mt][nt], Al[mt], Bh[bt][sub * 2], Bh[bt][sub * 2 + 1]);
          }
    }
    // epilogue: residual add + store
    #pragma unroll
    for (int mt = 0; mt < 2; mt++) {
      int c = cc * 128 + cy + mt * 16 + gI;
      #pragma unroll
      for (int nt = 0; nt < 8; nt++) {
        int n = n0 + nx + nt * 8 + 2 * tq;
        size_t off = ((size_t)(b * NC + c)) * NN + n;
        float2 xv0 = *(const float2*)(x + off);
        float2 xv1 = *(const float2*)(x + off + (size_t)8 * NN);
        float2 o0 = {fmaf(g, acc2[mt][nt][0], xv0.x), fmaf(g, acc2[mt][nt][1], xv0.y)};
        float2 o1 = {fmaf(g, acc2[mt][nt][2], xv1.x), fmaf(g, acc2[mt][nt][3], xv1.y)};
        *(float2*)(out + off) = o0;
        *(float2*)(out + off + (size_t)8 * NN) = o1;
      }
    }
  }
}

// ---------------- launch -----------------------------------------------------
extern "C" void kernel_launch(void* const* d_in, const int* in_sizes, int n_in,
                              void* d_out, int out_size) {
  const float* x     = (const float*)d_in[0];
  const float* Wq    = (const float*)d_in[1];
  const float* bq    = (const float*)d_in[2];
  const float* Wk    = (const float*)d_in[3];
  const float* bk    = (const float*)d_in[4];
  const float* Wv    = (const float*)d_in[5];
  const float* bv    = (const float*)d_in[6];
  const float* gamma = (const float*)d_in[7];
  const float* pe    = (const float*)d_in[8];
  const int*   pos   = (const int*)  d_in[9];
  float* out = (float*)d_out;

  static int smem_set = 0;
  if (!smem_set) {
    cudaFuncSetAttribute(k_fused, cudaFuncAttributeMaxDynamicSharedMemorySize,
                         SMEM_FUSED);
    smem_set = 1;
  }

  k_xbar<<<dim3(NC, NB), 256>>>(x);
  k_x2d<<<NB, NC>>>(pos, pe);
  k_gemmKV<<<dim3(12, NB, 4), 256>>>(Wk, Wv);
  k_reduceKV<<<(NB * (CKQ + NC) * NW + 255) / 256, 256>>>(bk, bv);
  k_gemmM<<<dim3(NC / 64, NB, 4), 256>>>(Wq);
  k_reduceM<<<513, 256>>>(bq);
  k_fused<<<dim3(NN / 128, NB), 256, SMEM_FUSED>>>(x, gamma, out);
}

// round 7
// speedup vs baseline: 1.7033x; 1.3803x over previous
#include <cuda_runtime.h>
#include <cuda_bf16.h>

#define NB 4
#define NC 512
#define CKQ 256
#define NW 64
#define NH 64
#define NN 4096   // H*W

// ---------------- scratch (device globals) ----------------------------------
__device__ float g_xbar[NB][NC][NW];
__device__ float g_x2d [NB][NC][NW];
__device__ float g_krow[NB][CKQ][NW];
__device__ float g_dw  [NB][NW];
__device__ float g_part[4][NB][CKQ + NC][NW];   // split-K partials (KV)
__device__ float g_pM  [4][NB][NW][NC];         // split-K partials (M, transposed)
__device__ __nv_bfloat16 g_MTh[NB][NW][NC];     // M^T hi/lo bf16
__device__ __nv_bfloat16 g_MTl[NB][NW][NC];
__device__ __nv_bfloat16 g_vbh[NB][NC][NW];     // vbar hi/lo bf16
__device__ __nv_bfloat16 g_vbl[NB][NC][NW];

// ---------------- helpers ----------------------------------------------------
__device__ __forceinline__ unsigned pack_bf2(float e, float o) {
  __nv_bfloat162 h;
  h.x = __float2bfloat16(e);
  h.y = __float2bfloat16(o);
  return *reinterpret_cast<unsigned*>(&h);
}
__device__ __forceinline__ void ldsm4(unsigned& r0, unsigned& r1, unsigned& r2,
                                      unsigned& r3, unsigned addr) {
  asm volatile("ldmatrix.sync.aligned.m8n8.x4.shared.b16 {%0,%1,%2,%3},[%4];"
               : "=r"(r0), "=r"(r1), "=r"(r2), "=r"(r3) : "r"(addr));
}
__device__ __forceinline__ void mma16816(float* d, const unsigned* a,
                                         unsigned b0, unsigned b1) {
  asm volatile(
    "mma.sync.aligned.m16n8k16.row.col.f32.bf16.bf16.f32 "
    "{%0,%1,%2,%3},{%4,%5,%6,%7},{%8,%9},{%0,%1,%2,%3};"
    : "+f"(d[0]), "+f"(d[1]), "+f"(d[2]), "+f"(d[3])
    : "r"(a[0]), "r"(a[1]), "r"(a[2]), "r"(a[3]), "r"(b0), "r"(b1));
}
__device__ __forceinline__ void cp16(unsigned saddr, const void* g) {
  asm volatile("cp.async.cg.shared.global [%0],[%1],16;" :: "r"(saddr), "l"(g));
}
#define CP_COMMIT() asm volatile("cp.async.commit_group;")
#define CP_WAIT(n)  asm volatile("cp.async.wait_group %0;" :: "n"(n))

// ---------------- K1: xbar = mean_h x, then x1d+PE interp to x2d ------------
__global__ void k_prep(const float* __restrict__ x, const int* __restrict__ pos,
                       const float* __restrict__ pe) {
  int c = blockIdx.x, b = blockIdx.y;
  int t = threadIdx.x;
  int hq = t >> 4, tw = t & 15;
  const float* xp = x + ((size_t)(b * NC + c)) * NH * NW;
  float4 s = {0.f, 0.f, 0.f, 0.f};
  #pragma unroll
  for (int h = hq; h < NH; h += 16) {
    float4 v = *(const float4*)&xp[h * NW + tw * 4];
    s.x += v.x; s.y += v.y; s.z += v.z; s.w += v.w;
  }
  __shared__ float4 sm4[16][16];
  __shared__ float xbv[64];
  __shared__ float x1s[16];
  __shared__ int pidx[16];
  sm4[hq][tw] = s;
  if (t < 16) pidx[t] = pos[b * NN + 4 * t] >> 3;
  __syncthreads();
  if (hq == 0) {
    float4 a = {0.f, 0.f, 0.f, 0.f};
    #pragma unroll
    for (int q = 0; q < 16; q++) {
      float4 v = sm4[q][tw];
      a.x += v.x; a.y += v.y; a.z += v.z; a.w += v.w;
    }
    const float inv = 1.0f / NH;
    a.x *= inv; a.y *= inv; a.z *= inv; a.w *= inv;
    *(float4*)&xbv[tw * 4] = a;
    *(float4*)&g_xbar[b][c][tw * 4] = a;
  }
  __syncthreads();
  if (t < 16)
    x1s[t] = 0.25f * (xbv[4 * t] + xbv[4 * t + 1] + xbv[4 * t + 2] + xbv[4 * t + 3])
             + pe[pidx[t] * NC + c];
  __syncthreads();
  if (t < NW) {
    float src = (t * 15.0f) / 63.0f;
    int   i0  = (int)floorf(src);
    int   i1  = min(i0 + 1, 15);
    float tt  = src - (float)i0;
    g_x2d[b][c][t] = x1s[i0] * (1.0f - tt) + x1s[i1] * tt;
  }
}

// ---------------- combined krow/vbar split-K GEMM ----------------------------
__global__ void k_gemmKV(const float* __restrict__ Wk, const float* __restrict__ Wv) {
  bool vb = (blockIdx.x >= 4);
  const float* A = vb ? Wv : Wk;
  const float* X = vb ? &g_xbar[0][0][0] : &g_x2d[0][0][0];
  int r0   = (vb ? (int)blockIdx.x - 4 : (int)blockIdx.x) * 64;
  int rout = vb ? CKQ + r0 : r0;
  int b = blockIdx.y, ks = blockIdx.z;
  int c0base = ks * 128;
  __shared__ float As[16][68];
  __shared__ float Xs[16][68];
  int tid = threadIdx.x, ty = tid >> 4, tx = tid & 15;
  float acc[4][4] = {};
  const float* Xb = X + (size_t)b * NC * NW;
  for (int c0 = c0base; c0 < c0base + 128; c0 += 16) {
    {
      int rr = tid >> 2, k4 = (tid & 3) * 4;
      float4 v = *(const float4*)(A + (size_t)(r0 + rr) * NC + c0 + k4);
      As[k4 + 0][rr] = v.x; As[k4 + 1][rr] = v.y;
      As[k4 + 2][rr] = v.z; As[k4 + 3][rr] = v.w;
    }
    {
      int kk = tid >> 4, w4 = (tid & 15) * 4;
      *(float4*)&Xs[kk][w4] = *(const float4*)(Xb + (c0 + kk) * NW + w4);
    }
    __syncthreads();
    #pragma unroll
    for (int kk = 0; kk < 16; kk++) {
      float av[4], bv[4];
      *(float4*)av = *(float4*)&As[kk][ty * 4];
      *(float4*)bv = *(float4*)&Xs[kk][tx * 4];
      #pragma unroll
      for (int i = 0; i < 4; i++)
        #pragma unroll
        for (int j = 0; j < 4; j++)
          acc[i][j] = fmaf(av[i], bv[j], acc[i][j]);
    }
    __syncthreads();
  }
  float* pp = &g_part[ks][b][rout][0];
  #pragma unroll
  for (int i = 0; i < 4; i++)
    *(float4*)&pp[(ty * 4 + i) * NW + tx * 4] = *(float4*)acc[i];
}

// ---------------- reduce krow/vbar; emit krow f32, vbar bf16 hi/lo ----------
__global__ void k_reduceKV(const float* __restrict__ bk, const float* __restrict__ bv) {
  int idx = blockIdx.x * 256 + threadIdx.x;
  const int total = NB * (CKQ + NC) * NW;
  if (idx >= total) return;
  int b = idx / ((CKQ + NC) * NW);
  int rw = idx - b * (CKQ + NC) * NW;
  int r = rw >> 6, w = idx & 63;
  float s = 0.f;
  #pragma unroll
  for (int ks = 0; ks < 4; ks++) s += (&g_part[ks][b][0][0])[rw];
  if (r < CKQ) {
    g_krow[b][r][w] = s + bk[r];
  } else {
    int c = r - CKQ;
    float v = s + bv[c];
    __nv_bfloat16 h = __float2bfloat16(v);
    g_vbh[b][c][w] = h;
    g_vbl[b][c][w] = __float2bfloat16(v - __bfloat162float(h));
  }
}

// ---------------- M^T parts = (Wq^T @ krow)^T --------------------------------
__global__ void k_gemmM(const float* __restrict__ Wq) {
  int b = blockIdx.y, ks = blockIdx.z;
  int r0 = blockIdx.x * 64;
  int c0base = ks * 64;
  __shared__ float As[16][68];
  __shared__ float Xs[16][68];
  int tid = threadIdx.x, ty = tid >> 4, tx = tid & 15;
  float acc[4][4] = {};
  for (int c0 = c0base; c0 < c0base + 64; c0 += 16) {
    {
      int kk = tid >> 4, r4 = (tid & 15) * 4;
      *(float4*)&As[kk][r4] = *(const float4*)(Wq + (size_t)(c0 + kk) * NC + r0 + r4);
    }
    {
      int kk = tid >> 4, w4 = (tid & 15) * 4;
      *(float4*)&Xs[kk][w4] = *(const float4*)(&g_krow[b][c0 + kk][w4]);
    }
    __syncthreads();
    #pragma unroll
    for (int kk = 0; kk < 16; kk++) {
      float av[4], bv[4];
      *(float4*)av = *(float4*)&As[kk][ty * 4];
      *(float4*)bv = *(float4*)&Xs[kk][tx * 4];
      #pragma unroll
      for (int i = 0; i < 4; i++)
        #pragma unroll
        for (int j = 0; j < 4; j++)
          acc[i][j] = fmaf(av[i], bv[j], acc[i][j]);
    }
    __syncthreads();
  }
  #pragma unroll
  for (int i = 0; i < 4; i++)
    #pragma unroll
    for (int j = 0; j < 4; j++)
      g_pM[ks][b][tx * 4 + j][r0 + ty * 4 + i] = acc[i][j];
}

// ---------------- reduce M^T parts -> bf16 hi/lo; extra block = dw -----------
__global__ void k_reduceM(const float* __restrict__ bq) {
  if (blockIdx.x == 512) {
    int t = threadIdx.x;
    int b = t >> 6, w = t & 63;
    float s = 0.f;
    #pragma unroll 4
    for (int o = 0; o < CKQ; o++) s += bq[o] * g_krow[b][o][w];
    g_dw[b][w] = s;
    return;
  }
  int idx = blockIdx.x * 256 + threadIdx.x;
  int b = idx >> 15;
  int rem = idx & 32767;
  float s = 0.f;
  #pragma unroll
  for (int ks = 0; ks < 4; ks++) s += (&g_pM[ks][b][0][0])[rem];
  __nv_bfloat16 h = __float2bfloat16(s);
  (&g_MTh[b][0][0])[rem] = h;
  (&g_MTl[b][0][0])[rem] = __float2bfloat16(s - __bfloat162float(h));
}

// ---------------- fused: E = x^T M + dw, softmax, out = g*(vbar@A^T)+x -------
// smem layout (all regions disjoint; double-buffered M and VB)
#define XA_H 0
#define XA_L 10240
#define MB0  20480
#define MBSZ 10240          // hi at +0 (5120), lo at +5120
#define OFF_E 40960         // 128*68*4 = 34816
#define ATT_H 75776
#define ATT_L 94208
#define VB0  112640
#define VBSZ 36864          // hi at +0 (18432), lo at +18432
#define SMEM_FUSED 186368

__global__ __launch_bounds__(256)
void k_fused(const float* __restrict__ x, const float* __restrict__ gamma,
             float* __restrict__ out) {
  extern __shared__ char sm[];
  unsigned sb = (unsigned)__cvta_generic_to_shared(sm);
  int tid = threadIdx.x;
  int wid = tid >> 5, lane = tid & 31;
  int b = blockIdx.y;
  int n0 = blockIdx.x * 128;
  int gI = lane >> 2, tq = lane & 3;

  const float* xb = x + (size_t)b * NC * NN + n0;
  // loader coords
  int lc2a = tid >> 5, ln4a = tid & 31;              // it = tid
  int lc2b = (tid + 256) >> 5, ln4b = tid & 31;      // it = tid+256
  int mw = tid >> 2, mq = tid & 3;                   // M cp coords

  float4 xr[4];                                      // x prefetch regs

  auto load_x = [&](int c0) {
    const float* p0 = xb + (size_t)(c0 + 2 * lc2a) * NN + ln4a * 4;
    xr[0] = *(const float4*)p0;
    xr[1] = *(const float4*)(p0 + NN);
    const float* p1 = xb + (size_t)(c0 + 2 * lc2b) * NN + ln4b * 4;
    xr[2] = *(const float4*)p1;
    xr[3] = *(const float4*)(p1 + NN);
  };
  auto store_x = [&]() {
    #pragma unroll
    for (int z = 0; z < 2; z++) {
      int c2 = z ? lc2b : lc2a;
      int n4 = z ? ln4b : ln4a;
      float a0[4] = {xr[2*z].x, xr[2*z].y, xr[2*z].z, xr[2*z].w};
      float a1[4] = {xr[2*z+1].x, xr[2*z+1].y, xr[2*z+1].z, xr[2*z+1].w};
      #pragma unroll
      for (int j = 0; j < 4; j++) {
        int n = n4 * 4 + j;
        float h0 = __bfloat162float(__float2bfloat16(a0[j]));
        float h1 = __bfloat162float(__float2bfloat16(a1[j]));
        ((unsigned*)(sm + XA_H))[n * 20 + c2] = pack_bf2(a0[j], a1[j]);
        ((unsigned*)(sm + XA_L))[n * 20 + c2] = pack_bf2(a0[j] - h0, a1[j] - h1);
      }
    }
  };
  auto issue_M = [&](int c0, unsigned mb) {
    cp16(sb + mb + mw * 80 + mq * 16,        &g_MTh[b][mw][c0 + mq * 8]);
    cp16(sb + mb + 5120 + mw * 80 + mq * 16, &g_MTl[b][mw][c0 + mq * 8]);
  };
  auto issue_VB = [&](int cc, unsigned base) {
    #pragma unroll
    for (int it2 = tid; it2 < 1024; it2 += 256) {
      int rr = it2 >> 3, q = it2 & 7;
      cp16(sb + base + rr * 144 + q * 16,         &g_vbh[b][cc * 128 + rr][q * 8]);
      cp16(sb + base + 18432 + rr * 144 + q * 16, &g_vbl[b][cc * 128 + rr][q * 8]);
    }
  };

  // ---------------- phase 1: E[128n][64w] -----------------------------------
  int ny = (wid >> 1) * 32;
  int wy = (wid & 1) * 32;
  float acc1[2][4][4] = {};

  // prologue: chunk 0
  load_x(0);
  issue_M(0, MB0);
  CP_COMMIT();
  store_x();
  CP_WAIT(0);
  __syncthreads();

  for (int i = 0; i < 16; i++) {
    if (i < 15) {
      load_x((i + 1) * 32);
      issue_M((i + 1) * 32, MB0 + ((i + 1) & 1) * MBSZ);
      CP_COMMIT();
    }
    unsigned mbb = MB0 + (i & 1) * MBSZ;
    #pragma unroll
    for (int ks = 0; ks < 32; ks += 16) {
      unsigned Ah[2][4], Al[2][4];
      #pragma unroll
      for (int mt = 0; mt < 2; mt++) {
        unsigned row = ny + mt * 16 + (lane & 15);
        unsigned coff = ks * 2 + ((lane >> 4) << 4);
        ldsm4(Ah[mt][0], Ah[mt][1], Ah[mt][2], Ah[mt][3], sb + XA_H + row * 80 + coff);
        ldsm4(Al[mt][0], Al[mt][1], Al[mt][2], Al[mt][3], sb + XA_L + row * 80 + coff);
      }
      unsigned Bh[2][4], Bl[2][4];
      #pragma unroll
      for (int bt = 0; bt < 2; bt++) {
        unsigned row = wy + bt * 16 + (lane & 7) + ((lane & 16) >> 1);
        unsigned coff = ks * 2 + ((lane & 8) << 1);
        ldsm4(Bh[bt][0], Bh[bt][1], Bh[bt][2], Bh[bt][3], sb + mbb + row * 80 + coff);
        ldsm4(Bl[bt][0], Bl[bt][1], Bl[bt][2], Bl[bt][3], sb + mbb + 5120 + row * 80 + coff);
      }
      #pragma unroll
      for (int mt = 0; mt < 2; mt++)
        #pragma unroll
        for (int bt = 0; bt < 2; bt++)
          #pragma unroll
          for (int sub = 0; sub < 2; sub++) {
            int wt = bt * 2 + sub;
            mma16816(acc1[mt][wt], Ah[mt], Bh[bt][sub * 2], Bh[bt][sub * 2 + 1]);
            mma16816(acc1[mt][wt], Ah[mt], Bl[bt][sub * 2], Bl[bt][sub * 2 + 1]);
            mma16816(acc1[mt][wt], Al[mt], Bh[bt][sub * 2], Bh[bt][sub * 2 + 1]);
          }
    }
    __syncthreads();
    if (i < 15) {
      store_x();
      CP_WAIT(0);
    }
    __syncthreads();
  }

  // prefetch VB chunk 0 (hidden under softmax/epilogue)
  issue_VB(0, VB0);
  CP_COMMIT();

  // epilogue: E += dw, stage to smem
  float* Ef = (float*)(sm + OFF_E);
  #pragma unroll
  for (int wt = 0; wt < 4; wt++) {
    int wc = wy + wt * 8 + 2 * tq;
    float d0 = g_dw[b][wc], d1 = g_dw[b][wc + 1];
    #pragma unroll
    for (int mt = 0; mt < 2; mt++) {
      int r = ny + mt * 16 + gI;
      float2 v0 = {acc1[mt][wt][0] + d0, acc1[mt][wt][1] + d1};
      float2 v1 = {acc1[mt][wt][2] + d0, acc1[mt][wt][3] + d1};
      *(float2*)&Ef[r * 68 + wc] = v0;
      *(float2*)&Ef[(r + 8) * 68 + wc] = v1;
    }
  }
  __syncthreads();

  // softmax over w (2 threads/row)
  {
    int row = tid >> 1, q = tid & 1;
    float mx = -1e30f;
    for (int w = q; w < NW; w += 2) mx = fmaxf(mx, Ef[row * 68 + w]);
    mx = fmaxf(mx, __shfl_xor_sync(0xffffffffu, mx, 1));
    float s = 0.f;
    for (int w = q; w < NW; w += 2) {
      float e = __expf(Ef[row * 68 + w] - mx);
      Ef[row * 68 + w] = e;
      s += e;
    }
    s += __shfl_xor_sync(0xffffffffu, s, 1);
    float inv = 1.0f / s;
    for (int w = q; w < NW; w += 2) Ef[row * 68 + w] *= inv;
  }
  __syncthreads();

  // convert attn to bf16 hi/lo
  #pragma unroll
  for (int i = 0; i < 16; i++) {
    int p = tid + i * 256;
    int n = p >> 5, wp = p & 31;
    float e0 = Ef[n * 68 + 2 * wp], e1 = Ef[n * 68 + 2 * wp + 1];
    float h0 = __bfloat162float(__float2bfloat16(e0));
    float h1 = __bfloat162float(__float2bfloat16(e1));
    ((unsigned*)(sm + ATT_H))[n * 36 + wp] = pack_bf2(e0, e1);
    ((unsigned*)(sm + ATT_L))[n * 36 + wp] = pack_bf2(e0 - h0, e1 - h1);
  }

  // ---------------- phase 2: out = gamma*(vbar @ A^T) + x --------------------
  float g = gamma[0];
  int cy = (wid >> 1) * 32;
  int nx = (wid & 1) * 64;
  for (int cc = 0; cc < 4; cc++) {
    if (cc < 3) {
      issue_VB(cc + 1, VB0 + ((cc + 1) & 1) * VBSZ);
      CP_COMMIT();
      CP_WAIT(1);
    } else {
      CP_WAIT(0);
    }
    __syncthreads();                 // VB(cc) visible; also orders ATT stores

    unsigned vbb = VB0 + (cc & 1) * VBSZ;
    float acc2[2][8][4] = {};
    #pragma unroll
    for (int ks = 0; ks < 64; ks += 16) {
      unsigned Ah[2][4], Al[2][4];
      #pragma unroll
      for (int mt = 0; mt < 2; mt++) {
        unsigned row = cy + mt * 16 + (lane & 15);
        unsigned coff = ks * 2 + ((lane >> 4) << 4);
        ldsm4(Ah[mt][0], Ah[mt][1], Ah[mt][2], Ah[mt][3], sb + vbb + row * 144 + coff);
        ldsm4(Al[mt][0], Al[mt][1], Al[mt][2], Al[mt][3], sb + vbb + 18432 + row * 144 + coff);
      }
      unsigned Bh[4][4], Bl[4][4];
      #pragma unroll
      for (int bt = 0; bt < 4; bt++) {
        unsigned row = nx + bt * 16 + (lane & 7) + ((lane & 16) >> 1);
        unsigned coff = ks * 2 + ((lane & 8) << 1);
        ldsm4(Bh[bt][0], Bh[bt][1], Bh[bt][2], Bh[bt][3], sb + ATT_H + row * 144 + coff);
        ldsm4(Bl[bt][0], Bl[bt][1], Bl[bt][2], Bl[bt][3], sb + ATT_L + row * 144 + coff);
      }
      #pragma unroll
      for (int mt = 0; mt < 2; mt++)
        #pragma unroll
        for (int bt = 0; bt < 4; bt++)
          #pragma unroll
          for (int sub = 0; sub < 2; sub++) {
            int nt = bt * 2 + sub;
            mma16816(acc2[mt][nt], Ah[mt], Bh[bt][sub * 2], Bh[bt][sub * 2 + 1]);
            mma16816(acc2[mt][nt], Ah[mt], Bl[bt][sub * 2], Bl[bt][sub * 2 + 1]);
            mma16816(acc2[mt][nt], Al[mt], Bh[bt][sub * 2], Bh[bt][sub * 2 + 1]);
          }
    }
    // epilogue: residual add + store
    #pragma unroll
    for (int mt = 0; mt < 2; mt++) {
      int c = cc * 128 + cy + mt * 16 + gI;
      #pragma unroll
      for (int nt = 0; nt < 8; nt++) {
        int n = n0 + nx + nt * 8 + 2 * tq;
        size_t off = ((size_t)(b * NC + c)) * NN + n;
        float2 xv0 = *(const float2*)(x + off);
        float2 xv1 = *(const float2*)(x + off + (size_t)8 * NN);
        float2 o0 = {fmaf(g, acc2[mt][nt][0], xv0.x), fmaf(g, acc2[mt][nt][1], xv0.y)};
        float2 o1 = {fmaf(g, acc2[mt][nt][2], xv1.x), fmaf(g, acc2[mt][nt][3], xv1.y)};
        *(float2*)(out + off) = o0;
        *(float2*)(out + off + (size_t)8 * NN) = o1;
      }
    }
    __syncthreads();                 // protect VB buffer before next overwrite
  }
}

// ---------------- launch -----------------------------------------------------
extern "C" void kernel_launch(void* const* d_in, const int* in_sizes, int n_in,
                              void* d_out, int out_size) {
  const float* x     = (const float*)d_in[0];
  const float* Wq    = (const float*)d_in[1];
  const float* bq    = (const float*)d_in[2];
  const float* Wk    = (const float*)d_in[3];
  const float* bk    = (const float*)d_in[4];
  const float* Wv    = (const float*)d_in[5];
  const float* bv    = (const float*)d_in[6];
  const float* gamma = (const float*)d_in[7];
  const float* pe    = (const float*)d_in[8];
  const int*   pos   = (const int*)  d_in[9];
  float* out = (float*)d_out;

  static int smem_set = 0;
  if (!smem_set) {
    cudaFuncSetAttribute(k_fused, cudaFuncAttributeMaxDynamicSharedMemorySize,
                         SMEM_FUSED);
    smem_set = 1;
  }

  k_prep<<<dim3(NC, NB), 256>>>(x, pos, pe);
  k_gemmKV<<<dim3(12, NB, 4), 256>>>(Wk, Wv);
  k_reduceKV<<<(NB * (CKQ + NC) * NW + 255) / 256, 256>>>(bk, bv);
  k_gemmM<<<dim3(NC / 64, NB, 4), 256>>>(Wq);
  k_reduceM<<<513, 256>>>(bq);
  k_fused<<<dim3(NN / 128, NB), 256, SMEM_FUSED>>>(x, gamma, out);
}